// round 12
// baseline (speedup 1.0000x reference)
#include <cuda_runtime.h>
#include <cuda_bf16.h>
#include <cstdint>

#define L 4096
#define D 576
#define DQKV 1728
#define NH 8
#define DH 72
#define OUTC 128

// Scratch (no dynamic allocation allowed)
__device__ float g_x[L * D];                       // fp32 tokens (residual)
__device__ __nv_bfloat16 g_xh[L * D], g_xl[L * D]; // split tokens
__device__ __nv_bfloat16 g_qkvh[L * DQKV];         // bf16 qkv, Q pre-scaled
__device__ __nv_bfloat16 g_attnh[L * D], g_attnl[L * D];
__device__ __nv_bfloat16 g_yh[L * D], g_yl[L * D];
__device__ __nv_bfloat16 g_wqh[D * DQKV], g_wql[D * DQKV];
__device__ __nv_bfloat16 g_woh[D * D], g_wol[D * D];
__device__ __nv_bfloat16 g_cwh[D * OUTC], g_cwl[D * OUTC];  // conv_w transposed [K][N]

#define CSCALE (0.11785113019775793f * 1.4426950408889634f)  // 72^-0.5 * log2e

// ---------------------------------------------------------------------------
// helpers
// ---------------------------------------------------------------------------
__device__ __forceinline__ uint32_t smem_u32(const void* p) {
    uint32_t a;
    asm("{ .reg .u64 t; cvta.to.shared.u64 t, %1; cvt.u32.u64 %0, t; }" : "=r"(a) : "l"(p));
    return a;
}

// Fast exp2 on FMA/ALU pipes (no MUFU). |x| < ~30. rel err ~2e-6.
__device__ __forceinline__ float fast_exp2(float x) {
    float t = __fadd_rn(x, 12582912.0f);
    int ni = __float_as_int(t) - 0x4B400000;
    float f = x - __fadd_rn(t, -12582912.0f);
    float y = f * 0.6931471805599453f;
    float p = 8.3333333e-3f;
    p = fmaf(p, y, 4.1666667e-2f);
    p = fmaf(p, y, 0.16666667f);
    p = fmaf(p, y, 0.5f);
    p = fmaf(p, y, 1.0f);
    p = fmaf(p, y, 1.0f);
    return __int_as_float(__float_as_int(p) + (ni << 23));
}

#define LDSM_X4(r0, r1, r2, r3, a) \
    asm volatile("ldmatrix.sync.aligned.m8n8.x4.shared.b16 {%0,%1,%2,%3}, [%4];" \
                 : "=r"(r0), "=r"(r1), "=r"(r2), "=r"(r3) : "r"(a))
#define LDSM_X2(r0, r1, a) \
    asm volatile("ldmatrix.sync.aligned.m8n8.x2.shared.b16 {%0,%1}, [%2];" \
                 : "=r"(r0), "=r"(r1) : "r"(a))
#define LDSM_X2T(r0, r1, a) \
    asm volatile("ldmatrix.sync.aligned.m8n8.x2.trans.shared.b16 {%0,%1}, [%2];" \
                 : "=r"(r0), "=r"(r1) : "r"(a))
#define MMA_BF16(c0, c1, c2, c3, a0, a1, a2, a3, b0, b1) \
    asm volatile("mma.sync.aligned.m16n8k16.row.col.f32.bf16.bf16.f32 " \
                 "{%0,%1,%2,%3}, {%4,%5,%6,%7}, {%8,%9}, {%0,%1,%2,%3};" \
                 : "+f"(c0), "+f"(c1), "+f"(c2), "+f"(c3) \
                 : "r"(a0), "r"(a1), "r"(a2), "r"(a3), "r"(b0), "r"(b1))
#define PACK_BF16X2(d, lo, hi) \
    asm("cvt.rn.bf16x2.f32 %0, %1, %2;" : "=r"(d) : "f"(hi), "f"(lo))
#define CP_ASYNC16(sm, gm) \
    asm volatile("cp.async.cg.shared.global [%0], [%1], 16;" :: "r"(sm), "l"(gm) : "memory")
#define CP_COMMIT() asm volatile("cp.async.commit_group;" ::: "memory")
#define CP_WAIT(n)  asm volatile("cp.async.wait_group %0;" :: "n"(n) : "memory")

// split (x,y) -> packed bf16x2 hi + lo-of-residual
__device__ __forceinline__ void split2(float x, float y, uint32_t& hi, uint32_t& lo) {
    __nv_bfloat16 xh = __float2bfloat16(x), yh = __float2bfloat16(y);
    float xr = x - __bfloat162float(xh), yr = y - __bfloat162float(yh);
    PACK_BF16X2(hi, __bfloat162float(xh), __bfloat162float(yh));
    PACK_BF16X2(lo, xr, yr);
}

// ---------------------------------------------------------------------------
// 1) unfold(3x3, pad=1, stride=2) -> x[L,576] fp32 + split bf16
// ---------------------------------------------------------------------------
__global__ void build_x_kernel(const float* __restrict__ fea) {
    int idx = blockIdx.x * blockDim.x + threadIdx.x;
    if (idx >= L * D) return;
    int l = idx / D, d = idx % D;
    int c = d / 9, k = d % 9;
    int ki = k / 3, kj = k % 3;
    int ho = l >> 6, wo = l & 63;
    int h = 2 * ho + ki - 1, w = 2 * wo + kj - 1;
    float v = 0.f;
    if ((unsigned)h < 128u && (unsigned)w < 128u)
        v = fea[(c << 14) + (h << 7) + w];
    g_x[idx] = v;
    __nv_bfloat16 hb = __float2bfloat16(v);
    g_xh[idx] = hb;
    g_xl[idx] = __float2bfloat16(v - __bfloat162float(hb));
}

// ---------------------------------------------------------------------------
// 1b) pre-split weights (w_qkv, w_out row-major [K][N]; conv_w transposed)
// ---------------------------------------------------------------------------
#define NW1 (D * DQKV)
#define NW2 (D * D)
#define NW3 (OUTC * D)
__global__ void split_w_kernel(const float* __restrict__ w_qkv,
                               const float* __restrict__ w_out,
                               const float* __restrict__ conv_w) {
    int i = blockIdx.x * blockDim.x + threadIdx.x;
    if (i < NW1) {
        float v = w_qkv[i];
        __nv_bfloat16 hb = __float2bfloat16(v);
        g_wqh[i] = hb;
        g_wql[i] = __float2bfloat16(v - __bfloat162float(hb));
    } else if (i < NW1 + NW2) {
        int e = i - NW1;
        float v = w_out[e];
        __nv_bfloat16 hb = __float2bfloat16(v);
        g_woh[e] = hb;
        g_wol[e] = __float2bfloat16(v - __bfloat162float(hb));
    } else if (i < NW1 + NW2 + NW3) {
        int e = i - NW1 - NW2;
        int n = e / D, k = e % D;       // conv_w [OUTC][D]
        float v = conv_w[e];
        __nv_bfloat16 hb = __float2bfloat16(v);
        int o = k * OUTC + n;           // -> [K][N]
        g_cwh[o] = hb;
        g_cwl[o] = __float2bfloat16(v - __bfloat162float(hb));
    }
}

// ---------------------------------------------------------------------------
// 2) Split-bf16 tensor-core GEMM, cp.async 2-stage pipeline.
//    All operands pre-split bf16. BM=128, BN=64, BK=32, 256 thr, 4x2 warps.
// MODE 0: C0(bf16) = A@B + bias, cols<576 scaled by CSCALE   (qkv)
// MODE 1: split(A@B + bias + resid_fp32) -> C0(h), C1(l)     (y)
// MODE 2: C0(fp32) = silu(A@B) stored transposed C0[n*M+m]   (out)
// ---------------------------------------------------------------------------
#define ASTR 40
#define BSTR 72
#define AH_O 0
#define AL_O (128 * ASTR)                  // 5120
#define BH_O (2 * 128 * ASTR)              // 10240
#define BL_O (2 * 128 * ASTR + 32 * BSTR)  // 12544
#define STAGE_EL (2 * 128 * ASTR + 2 * 32 * BSTR)  // 14848
#define GEMM_SMEM (STAGE_EL * 2 * 2)       // 59392 bytes

template <int MODE>
__global__ __launch_bounds__(256, 2)
void gemm_mma(const __nv_bfloat16* __restrict__ Ah, const __nv_bfloat16* __restrict__ Al,
              const __nv_bfloat16* __restrict__ Bh, const __nv_bfloat16* __restrict__ Bl,
              const float* __restrict__ bias, const float* __restrict__ resid,
              void* __restrict__ C0, void* __restrict__ C1, int M, int N, int K) {
    extern __shared__ __nv_bfloat16 sm[];
    const uint32_t base = smem_u32(sm);

    const int tid = threadIdx.x;
    const int w = tid >> 5, lane = tid & 31;
    const int wm = w & 3, wn = w >> 2;
    const int g = lane >> 2, tg = lane & 3;
    const int bm = blockIdx.y * 128, bn = blockIdx.x * 64;

    float acc[2][4][4];
#pragma unroll
    for (int i = 0; i < 2; i++)
#pragma unroll
        for (int n = 0; n < 4; n++)
#pragma unroll
            for (int c = 0; c < 4; c++) acc[i][n][c] = 0.f;

    const int a_row = wm * 32 + (lane & 15);
    const int a_colp = 8 * (lane >> 4);
    const int b_row = lane & 15;
    const int NIT = K / 32;

    auto prefetch = [&](int it) {
        const int k0 = it * 32;
        const uint32_t st = base + (uint32_t)((it & 1) * STAGE_EL * 2);
        // A: 1024 16B chunks (hi 512 + lo 512), 4 per thread
#pragma unroll
        for (int t = 0; t < 4; t++) {
            int idx = tid + t * 256;
            int arr = idx >> 9;
            int rem = idx & 511;
            int r = rem >> 2, ch = rem & 3;
            const __nv_bfloat16* src = (arr ? Al : Ah) + (size_t)(bm + r) * K + k0 + ch * 8;
            CP_ASYNC16(st + (uint32_t)((arr ? AL_O : AH_O) + r * ASTR + ch * 8) * 2, src);
        }
        // B: 512 chunks, 2 per thread
#pragma unroll
        for (int t = 0; t < 2; t++) {
            int idx = tid + t * 256;
            int arr = idx >> 8;
            int rem = idx & 255;
            int r = rem >> 3, ch = rem & 7;
            const __nv_bfloat16* src = (arr ? Bl : Bh) + (size_t)(k0 + r) * N + bn + ch * 8;
            CP_ASYNC16(st + (uint32_t)((arr ? BL_O : BH_O) + r * BSTR + ch * 8) * 2, src);
        }
        CP_COMMIT();
    };

    prefetch(0);

    for (int it = 0; it < NIT; it++) {
        if (it + 1 < NIT) { prefetch(it + 1); CP_WAIT(1); }
        else              { CP_WAIT(0); }
        __syncthreads();

        const uint32_t st = base + (uint32_t)((it & 1) * STAGE_EL * 2);
        const uint32_t ah = st + AH_O * 2, al = st + AL_O * 2;
        const uint32_t bh = st + BH_O * 2, bl = st + BL_O * 2;

#pragma unroll
        for (int s = 0; s < 2; s++) {
            uint32_t afh[2][4], afl[2][4];
#pragma unroll
            for (int i = 0; i < 2; i++) {
                uint32_t off = (uint32_t)((a_row + i * 16) * ASTR + s * 16 + a_colp) * 2;
                LDSM_X4(afh[i][0], afh[i][1], afh[i][2], afh[i][3], ah + off);
                LDSM_X4(afl[i][0], afl[i][1], afl[i][2], afl[i][3], al + off);
            }
            uint32_t bfh[4][2], bfl[4][2];
#pragma unroll
            for (int n = 0; n < 4; n++) {
                uint32_t off = (uint32_t)((s * 16 + b_row) * BSTR + wn * 32 + n * 8) * 2;
                LDSM_X2T(bfh[n][0], bfh[n][1], bh + off);
                LDSM_X2T(bfl[n][0], bfl[n][1], bl + off);
            }
#pragma unroll
            for (int i = 0; i < 2; i++)
#pragma unroll
                for (int n = 0; n < 4; n++) {
                    MMA_BF16(acc[i][n][0], acc[i][n][1], acc[i][n][2], acc[i][n][3],
                             afh[i][0], afh[i][1], afh[i][2], afh[i][3],
                             bfh[n][0], bfh[n][1]);
                    MMA_BF16(acc[i][n][0], acc[i][n][1], acc[i][n][2], acc[i][n][3],
                             afh[i][0], afh[i][1], afh[i][2], afh[i][3],
                             bfl[n][0], bfl[n][1]);
                    MMA_BF16(acc[i][n][0], acc[i][n][1], acc[i][n][2], acc[i][n][3],
                             afl[i][0], afl[i][1], afl[i][2], afl[i][3],
                             bfh[n][0], bfh[n][1]);
                }
        }
        __syncthreads();
    }

    // ---- epilogue ----
#pragma unroll
    for (int i = 0; i < 2; i++) {
        int row0 = bm + wm * 32 + i * 16 + g;
#pragma unroll
        for (int n = 0; n < 4; n++) {
            int col = bn + wn * 32 + n * 8 + 2 * tg;
            if (MODE == 0) {
                float b0 = bias[col], b1 = bias[col + 1];
                float sc = (col < D) ? CSCALE : 1.0f;
                __nv_bfloat16* Cb = (__nv_bfloat16*)C0;
                uint32_t u;
                PACK_BF16X2(u, (acc[i][n][0] + b0) * sc, (acc[i][n][1] + b1) * sc);
                *(uint32_t*)(Cb + (size_t)row0 * N + col) = u;
                PACK_BF16X2(u, (acc[i][n][2] + b0) * sc, (acc[i][n][3] + b1) * sc);
                *(uint32_t*)(Cb + (size_t)(row0 + 8) * N + col) = u;
            } else if (MODE == 1) {
                float b0 = bias[col], b1 = bias[col + 1];
                float2 r0 = *(const float2*)(resid + (size_t)row0 * N + col);
                float2 r1 = *(const float2*)(resid + (size_t)(row0 + 8) * N + col);
                __nv_bfloat16* Yh = (__nv_bfloat16*)C0;
                __nv_bfloat16* Yl = (__nv_bfloat16*)C1;
                uint32_t uh, ul;
                split2(acc[i][n][0] + b0 + r0.x, acc[i][n][1] + b1 + r0.y, uh, ul);
                *(uint32_t*)(Yh + (size_t)row0 * N + col) = uh;
                *(uint32_t*)(Yl + (size_t)row0 * N + col) = ul;
                split2(acc[i][n][2] + b0 + r1.x, acc[i][n][3] + b1 + r1.y, uh, ul);
                *(uint32_t*)(Yh + (size_t)(row0 + 8) * N + col) = uh;
                *(uint32_t*)(Yl + (size_t)(row0 + 8) * N + col) = ul;
            } else {
                float* Cf = (float*)C0;
                float v0 = acc[i][n][0], v1 = acc[i][n][1];
                float v2 = acc[i][n][2], v3 = acc[i][n][3];
                v0 = v0 / (1.f + __expf(-v0));
                v1 = v1 / (1.f + __expf(-v1));
                v2 = v2 / (1.f + __expf(-v2));
                v3 = v3 / (1.f + __expf(-v3));
                Cf[(size_t)col * M + row0] = v0;
                Cf[(size_t)(col + 1) * M + row0] = v1;
                Cf[(size_t)col * M + row0 + 8] = v2;
                Cf[(size_t)(col + 1) * M + row0 + 8] = v3;
            }
        }
    }
}

// ---------------------------------------------------------------------------
// 3) bf16 mma.sync flash attention, cp.async double-buffered (R9),
//    epilogue now emits split bf16 attn (h/l).
// ---------------------------------------------------------------------------
#define KT 64
#define SSTR 88
#define VOFF (64 * SSTR)

__global__ __launch_bounds__(256, 2)
void flash_attn_mma(const __nv_bfloat16* __restrict__ qkvh,
                    __nv_bfloat16* __restrict__ attnh,
                    __nv_bfloat16* __restrict__ attnl) {
    __shared__ __nv_bfloat16 R0[128 * SSTR];
    __shared__ __nv_bfloat16 R1[128 * SSTR];

    const int tid = threadIdx.x;
    const int w = tid >> 5, lane = tid & 31;
    const int g = lane >> 2, tg = lane & 3;
    const int head = blockIdx.y;
    const int q0 = blockIdx.x * 128;

    const uint32_t r0s = smem_u32(R0), r1s = smem_u32(R1);

    for (int i = tid; i < 128 * 4; i += 256) {
        int r = i >> 2, c = (i & 3) << 1;
        *(uint32_t*)&R0[r * SSTR + 72 + c] = 0;
        if (r < KT) *(uint32_t*)&R1[r * SSTR + 72 + c] = 0;
    }

    {
        const char* gq = (const char*)(qkvh + (size_t)q0 * DQKV + head * DH);
        for (int idx = tid; idx < 128 * 9; idx += 256) {
            int r = idx / 9, ch = idx % 9;
            CP_ASYNC16(r0s + (uint32_t)(r * SSTR * 2 + ch * 16),
                       gq + (size_t)r * (DQKV * 2) + ch * 16);
        }
        CP_COMMIT();
    }
    {
        const char* gk = (const char*)(qkvh + D + head * DH);
        for (int idx = tid; idx < 2 * KT * 9; idx += 256) {
            int part = idx >= KT * 9;
            int rem = idx - part * KT * 9;
            int r = rem / 9, ch = rem % 9;
            CP_ASYNC16(r1s + (uint32_t)(part * VOFF * 2 + r * SSTR * 2 + ch * 16),
                       gk + (size_t)r * (DQKV * 2) + (size_t)part * (D * 2) + ch * 16);
        }
        CP_COMMIT();
    }
    CP_WAIT(0);
    __syncthreads();

    uint32_t qa[5][4];
    {
        int row = w * 16 + (lane & 7) + 8 * ((lane >> 3) & 1);
        int colp = 8 * (lane >> 4);
#pragma unroll
        for (int s = 0; s < 5; s++) {
            uint32_t a = r0s + (uint32_t)(row * SSTR + 16 * s + colp) * 2;
            LDSM_X4(qa[s][0], qa[s][1], qa[s][2], qa[s][3], a);
        }
    }
    __syncthreads();

    float oacc[9][4];
#pragma unroll
    for (int n = 0; n < 9; n++)
#pragma unroll
        for (int i = 0; i < 4; i++) oacc[n][i] = 0.f;
    float l0 = 0.f, l1 = 0.f;

    const int bl_row = lane & 7;
    const int bl_colp = 8 * ((lane >> 3) & 1);
    const int vt_row = lane & 15;

    for (int kb = 0; kb < L / KT; kb++) {
        if (kb + 1 < L / KT) {
            uint32_t dst = ((kb + 1) & 1) ? r0s : r1s;
            const char* gk = (const char*)(qkvh + (size_t)((kb + 1) * KT) * DQKV + D + head * DH);
            for (int idx = tid; idx < 2 * KT * 9; idx += 256) {
                int part = idx >= KT * 9;
                int rem = idx - part * KT * 9;
                int r = rem / 9, ch = rem % 9;
                CP_ASYNC16(dst + (uint32_t)(part * VOFF * 2 + r * SSTR * 2 + ch * 16),
                           gk + (size_t)r * (DQKV * 2) + (size_t)part * (D * 2) + ch * 16);
            }
            CP_COMMIT();
            CP_WAIT(1);
        } else {
            CP_WAIT(0);
        }
        __syncthreads();

        const uint32_t kbuf = (kb & 1) ? r0s : r1s;
        const uint32_t vbuf = kbuf + VOFF * 2;

        float sacc[8][4];
#pragma unroll
        for (int j = 0; j < 8; j++) {
#pragma unroll
            for (int i = 0; i < 4; i++) sacc[j][i] = 0.f;
#pragma unroll
            for (int s = 0; s < 5; s++) {
                uint32_t b0, b1;
                uint32_t a = kbuf + (uint32_t)((j * 8 + bl_row) * SSTR + 16 * s + bl_colp) * 2;
                LDSM_X2(b0, b1, a);
                MMA_BF16(sacc[j][0], sacc[j][1], sacc[j][2], sacc[j][3],
                         qa[s][0], qa[s][1], qa[s][2], qa[s][3], b0, b1);
            }
        }

        uint32_t pa[8], pb[8];
#pragma unroll
        for (int j = 0; j < 8; j++) {
            float p0 = fast_exp2(sacc[j][0]);
            float p1 = fast_exp2(sacc[j][1]);
            float p2 = fast_exp2(sacc[j][2]);
            float p3 = fast_exp2(sacc[j][3]);
            l0 += p0 + p1;
            l1 += p2 + p3;
            PACK_BF16X2(pa[j], p0, p1);
            PACK_BF16X2(pb[j], p2, p3);
        }

#pragma unroll
        for (int t = 0; t < 4; t++) {
            uint32_t a0 = pa[2 * t], a1 = pb[2 * t];
            uint32_t a2 = pa[2 * t + 1], a3 = pb[2 * t + 1];
#pragma unroll
            for (int n = 0; n < 9; n++) {
                uint32_t b0, b1;
                uint32_t a = vbuf + (uint32_t)((16 * t + vt_row) * SSTR + 8 * n) * 2;
                LDSM_X2T(b0, b1, a);
                MMA_BF16(oacc[n][0], oacc[n][1], oacc[n][2], oacc[n][3],
                         a0, a1, a2, a3, b0, b1);
            }
        }
        __syncthreads();
    }

    l0 += __shfl_xor_sync(0xffffffffu, l0, 1);
    l0 += __shfl_xor_sync(0xffffffffu, l0, 2);
    l1 += __shfl_xor_sync(0xffffffffu, l1, 1);
    l1 += __shfl_xor_sync(0xffffffffu, l1, 2);
    float inv0 = 1.f / l0, inv1 = 1.f / l1;

    int row0 = q0 + w * 16 + g;
    size_t e0 = (size_t)row0 * D + head * DH + 2 * tg;
    size_t e1 = e0 + 8 * (size_t)D;
#pragma unroll
    for (int n = 0; n < 9; n++) {
        uint32_t uh, ul;
        split2(oacc[n][0] * inv0, oacc[n][1] * inv0, uh, ul);
        *(uint32_t*)(attnh + e0 + 8 * n) = uh;
        *(uint32_t*)(attnl + e0 + 8 * n) = ul;
        split2(oacc[n][2] * inv1, oacc[n][3] * inv1, uh, ul);
        *(uint32_t*)(attnh + e1 + 8 * n) = uh;
        *(uint32_t*)(attnl + e1 + 8 * n) = ul;
    }
}

// ---------------------------------------------------------------------------
extern "C" void kernel_launch(void* const* d_in, const int* in_sizes, int n_in,
                              void* d_out, int out_size) {
    const float* fea    = (const float*)d_in[0];
    const float* w_qkv  = (const float*)d_in[1];
    const float* b_qkv  = (const float*)d_in[2];
    const float* w_out  = (const float*)d_in[3];
    const float* b_out  = (const float*)d_in[4];
    const float* conv_w = (const float*)d_in[5];
    float* out = (float*)d_out;

    float* px;
    __nv_bfloat16 *pxh, *pxl, *pqkvh, *pah, *pal, *pyh, *pyl;
    __nv_bfloat16 *pwqh, *pwql, *pwoh, *pwol, *pcwh, *pcwl;
    cudaGetSymbolAddress((void**)&px,    g_x);
    cudaGetSymbolAddress((void**)&pxh,   g_xh);
    cudaGetSymbolAddress((void**)&pxl,   g_xl);
    cudaGetSymbolAddress((void**)&pqkvh, g_qkvh);
    cudaGetSymbolAddress((void**)&pah,   g_attnh);
    cudaGetSymbolAddress((void**)&pal,   g_attnl);
    cudaGetSymbolAddress((void**)&pyh,   g_yh);
    cudaGetSymbolAddress((void**)&pyl,   g_yl);
    cudaGetSymbolAddress((void**)&pwqh,  g_wqh);
    cudaGetSymbolAddress((void**)&pwql,  g_wql);
    cudaGetSymbolAddress((void**)&pwoh,  g_woh);
    cudaGetSymbolAddress((void**)&pwol,  g_wol);
    cudaGetSymbolAddress((void**)&pcwh,  g_cwh);
    cudaGetSymbolAddress((void**)&pcwl,  g_cwl);

    cudaFuncSetAttribute(gemm_mma<0>, cudaFuncAttributeMaxDynamicSharedMemorySize, GEMM_SMEM);
    cudaFuncSetAttribute(gemm_mma<1>, cudaFuncAttributeMaxDynamicSharedMemorySize, GEMM_SMEM);
    cudaFuncSetAttribute(gemm_mma<2>, cudaFuncAttributeMaxDynamicSharedMemorySize, GEMM_SMEM);

    // 1) unfold -> x (fp32 + split bf16); pre-split weights
    build_x_kernel<<<(L * D + 255) / 256, 256>>>(fea);
    split_w_kernel<<<(NW1 + NW2 + NW3 + 255) / 256, 256>>>(w_qkv, w_out, conv_w);

    // 2) qkv = x @ w_qkv + b_qkv -> bf16, Q pre-scaled
    gemm_mma<0><<<dim3(DQKV / 64, L / 128), 256, GEMM_SMEM>>>(
        pxh, pxl, pwqh, pwql, b_qkv, nullptr, (void*)pqkvh, nullptr, L, DQKV, D);

    // 3) attention -> split bf16 attn
    flash_attn_mma<<<dim3(L / 128, NH), 256>>>(pqkvh, pah, pal);

    // 4) y = attn @ w_out + b_out + x -> split bf16 y
    gemm_mma<1><<<dim3(D / 64, L / 128), 256, GEMM_SMEM>>>(
        pah, pal, pwoh, pwol, b_out, px, (void*)pyh, (void*)pyl, L, D, D);

    // 5) out = silu(y @ conv_w^T) stored as [128, 4096]
    gemm_mma<2><<<dim3(OUTC / 64, L / 128), 256, GEMM_SMEM>>>(
        pyh, pyl, pcwh, pcwl, nullptr, nullptr, (void*)out, nullptr, L, OUTC, D);
}

// round 14
// speedup vs baseline: 1.5210x; 1.5210x over previous
#include <cuda_runtime.h>
#include <cuda_bf16.h>
#include <cstdint>

#define L 4096
#define D 576
#define DQKV 1728
#define NH 8
#define DH 72
#define OUTC 128

// Scratch (no dynamic allocation allowed)
__device__ float g_x[L * D];                       // fp32 tokens (residual)
__device__ __nv_bfloat16 g_xh[L * D], g_xl[L * D]; // split tokens
__device__ __nv_bfloat16 g_qkvh[L * DQKV];         // bf16 qkv, Q pre-scaled
__device__ float g_attn[L * D];                    // fp32 attention output
__device__ __nv_bfloat16 g_attnh[L * D], g_attnl[L * D];
__device__ __nv_bfloat16 g_yh[L * D], g_yl[L * D];
__device__ __nv_bfloat16 g_wqh[D * DQKV], g_wql[D * DQKV];
__device__ __nv_bfloat16 g_woh[D * D], g_wol[D * D];
__device__ __nv_bfloat16 g_cwh[D * OUTC], g_cwl[D * OUTC];  // conv_w transposed [K][N]

#define CSCALE (0.11785113019775793f * 1.4426950408889634f)  // 72^-0.5 * log2e

// ---------------------------------------------------------------------------
// helpers
// ---------------------------------------------------------------------------
__device__ __forceinline__ uint32_t smem_u32(const void* p) {
    uint32_t a;
    asm("{ .reg .u64 t; cvta.to.shared.u64 t, %1; cvt.u32.u64 %0, t; }" : "=r"(a) : "l"(p));
    return a;
}

// Fast exp2 on FMA/ALU pipes (no MUFU). |x| < ~30. rel err ~2e-6.
__device__ __forceinline__ float fast_exp2(float x) {
    float t = __fadd_rn(x, 12582912.0f);
    int ni = __float_as_int(t) - 0x4B400000;
    float f = x - __fadd_rn(t, -12582912.0f);
    float y = f * 0.6931471805599453f;
    float p = 8.3333333e-3f;
    p = fmaf(p, y, 4.1666667e-2f);
    p = fmaf(p, y, 0.16666667f);
    p = fmaf(p, y, 0.5f);
    p = fmaf(p, y, 1.0f);
    p = fmaf(p, y, 1.0f);
    return __int_as_float(__float_as_int(p) + (ni << 23));
}

#define LDSM_X4(r0, r1, r2, r3, a) \
    asm volatile("ldmatrix.sync.aligned.m8n8.x4.shared.b16 {%0,%1,%2,%3}, [%4];" \
                 : "=r"(r0), "=r"(r1), "=r"(r2), "=r"(r3) : "r"(a))
#define LDSM_X2(r0, r1, a) \
    asm volatile("ldmatrix.sync.aligned.m8n8.x2.shared.b16 {%0,%1}, [%2];" \
                 : "=r"(r0), "=r"(r1) : "r"(a))
#define LDSM_X2T(r0, r1, a) \
    asm volatile("ldmatrix.sync.aligned.m8n8.x2.trans.shared.b16 {%0,%1}, [%2];" \
                 : "=r"(r0), "=r"(r1) : "r"(a))
#define MMA_BF16(c0, c1, c2, c3, a0, a1, a2, a3, b0, b1) \
    asm volatile("mma.sync.aligned.m16n8k16.row.col.f32.bf16.bf16.f32 " \
                 "{%0,%1,%2,%3}, {%4,%5,%6,%7}, {%8,%9}, {%0,%1,%2,%3};" \
                 : "+f"(c0), "+f"(c1), "+f"(c2), "+f"(c3) \
                 : "r"(a0), "r"(a1), "r"(a2), "r"(a3), "r"(b0), "r"(b1))
#define PACK_BF16X2(d, lo, hi) \
    asm("cvt.rn.bf16x2.f32 %0, %1, %2;" : "=r"(d) : "f"(hi), "f"(lo))
#define CP_ASYNC16(sm, gm) \
    asm volatile("cp.async.cg.shared.global [%0], [%1], 16;" :: "r"(sm), "l"(gm) : "memory")
#define CP_COMMIT() asm volatile("cp.async.commit_group;" ::: "memory")
#define CP_WAIT(n)  asm volatile("cp.async.wait_group %0;" :: "n"(n) : "memory")

// split (x,y) -> packed bf16x2 hi + lo-of-residual
__device__ __forceinline__ void split2(float x, float y, uint32_t& hi, uint32_t& lo) {
    __nv_bfloat16 xh = __float2bfloat16(x), yh = __float2bfloat16(y);
    float xr = x - __bfloat162float(xh), yr = y - __bfloat162float(yh);
    PACK_BF16X2(hi, __bfloat162float(xh), __bfloat162float(yh));
    PACK_BF16X2(lo, xr, yr);
}

// ---------------------------------------------------------------------------
// 1) unfold(3x3, pad=1, stride=2) -> x[L,576] fp32 + split bf16
// ---------------------------------------------------------------------------
__global__ void build_x_kernel(const float* __restrict__ fea) {
    int idx = blockIdx.x * blockDim.x + threadIdx.x;
    if (idx >= L * D) return;
    int l = idx / D, d = idx % D;
    int c = d / 9, k = d % 9;
    int ki = k / 3, kj = k % 3;
    int ho = l >> 6, wo = l & 63;
    int h = 2 * ho + ki - 1, w = 2 * wo + kj - 1;
    float v = 0.f;
    if ((unsigned)h < 128u && (unsigned)w < 128u)
        v = fea[(c << 14) + (h << 7) + w];
    g_x[idx] = v;
    __nv_bfloat16 hb = __float2bfloat16(v);
    g_xh[idx] = hb;
    g_xl[idx] = __float2bfloat16(v - __bfloat162float(hb));
}

// ---------------------------------------------------------------------------
// 1b) pre-split weights (w_qkv, w_out row-major [K][N]; conv_w transposed)
// ---------------------------------------------------------------------------
#define NW1 (D * DQKV)
#define NW2 (D * D)
#define NW3 (OUTC * D)
__global__ void split_w_kernel(const float* __restrict__ w_qkv,
                               const float* __restrict__ w_out,
                               const float* __restrict__ conv_w) {
    int i = blockIdx.x * blockDim.x + threadIdx.x;
    if (i < NW1) {
        float v = w_qkv[i];
        __nv_bfloat16 hb = __float2bfloat16(v);
        g_wqh[i] = hb;
        g_wql[i] = __float2bfloat16(v - __bfloat162float(hb));
    } else if (i < NW1 + NW2) {
        int e = i - NW1;
        float v = w_out[e];
        __nv_bfloat16 hb = __float2bfloat16(v);
        g_woh[e] = hb;
        g_wol[e] = __float2bfloat16(v - __bfloat162float(hb));
    } else if (i < NW1 + NW2 + NW3) {
        int e = i - NW1 - NW2;
        int n = e / D, k = e % D;       // conv_w [OUTC][D]
        float v = conv_w[e];
        __nv_bfloat16 hb = __float2bfloat16(v);
        int o = k * OUTC + n;           // -> [K][N]
        g_cwh[o] = hb;
        g_cwl[o] = __float2bfloat16(v - __bfloat162float(hb));
    }
}

// ---------------------------------------------------------------------------
// 1c) split attn fp32 -> bf16 h/l (keeps flash epilogue register-light)
// ---------------------------------------------------------------------------
__global__ void split_attn_kernel(const float* __restrict__ a,
                                  __nv_bfloat16* __restrict__ h,
                                  __nv_bfloat16* __restrict__ l) {
    int i = (blockIdx.x * blockDim.x + threadIdx.x) * 4;
    if (i >= L * D) return;
    float4 v = *(const float4*)(a + i);
    uint32_t uh0, ul0, uh1, ul1;
    split2(v.x, v.y, uh0, ul0);
    split2(v.z, v.w, uh1, ul1);
    *(uint32_t*)(h + i)     = uh0;
    *(uint32_t*)(h + i + 2) = uh1;
    *(uint32_t*)(l + i)     = ul0;
    *(uint32_t*)(l + i + 2) = ul1;
}

// ---------------------------------------------------------------------------
// 2) Split-bf16 tensor-core GEMM, cp.async 2-stage pipeline.
//    All operands pre-split bf16. BM=128, BN=64, BK=32, 256 thr, 4x2 warps.
// MODE 0: C0(bf16) = A@B + bias, cols<576 scaled by CSCALE   (qkv)
// MODE 1: split(A@B + bias + resid_fp32) -> C0(h), C1(l)     (y)
// MODE 2: C0(fp32) = silu(A@B) stored transposed C0[n*M+m]   (out)
// ---------------------------------------------------------------------------
#define ASTR 40
#define BSTR 72
#define AH_O 0
#define AL_O (128 * ASTR)                  // 5120
#define BH_O (2 * 128 * ASTR)              // 10240
#define BL_O (2 * 128 * ASTR + 32 * BSTR)  // 12544
#define STAGE_EL (2 * 128 * ASTR + 2 * 32 * BSTR)  // 14848
#define GEMM_SMEM (STAGE_EL * 2 * 2)       // 59392 bytes

template <int MODE>
__global__ __launch_bounds__(256, 2)
void gemm_mma(const __nv_bfloat16* __restrict__ Ah, const __nv_bfloat16* __restrict__ Al,
              const __nv_bfloat16* __restrict__ Bh, const __nv_bfloat16* __restrict__ Bl,
              const float* __restrict__ bias, const float* __restrict__ resid,
              void* __restrict__ C0, void* __restrict__ C1, int M, int N, int K) {
    extern __shared__ __nv_bfloat16 sm[];
    const uint32_t base = smem_u32(sm);

    const int tid = threadIdx.x;
    const int w = tid >> 5, lane = tid & 31;
    const int wm = w & 3, wn = w >> 2;
    const int g = lane >> 2, tg = lane & 3;
    const int bm = blockIdx.y * 128, bn = blockIdx.x * 64;

    float acc[2][4][4];
#pragma unroll
    for (int i = 0; i < 2; i++)
#pragma unroll
        for (int n = 0; n < 4; n++)
#pragma unroll
            for (int c = 0; c < 4; c++) acc[i][n][c] = 0.f;

    const int a_row = wm * 32 + (lane & 15);
    const int a_colp = 8 * (lane >> 4);
    const int b_row = lane & 15;
    const int NIT = K / 32;

    auto prefetch = [&](int it) {
        const int k0 = it * 32;
        const uint32_t st = base + (uint32_t)((it & 1) * STAGE_EL * 2);
#pragma unroll
        for (int t = 0; t < 4; t++) {
            int idx = tid + t * 256;
            int arr = idx >> 9;
            int rem = idx & 511;
            int r = rem >> 2, ch = rem & 3;
            const __nv_bfloat16* src = (arr ? Al : Ah) + (size_t)(bm + r) * K + k0 + ch * 8;
            CP_ASYNC16(st + (uint32_t)((arr ? AL_O : AH_O) + r * ASTR + ch * 8) * 2, src);
        }
#pragma unroll
        for (int t = 0; t < 2; t++) {
            int idx = tid + t * 256;
            int arr = idx >> 8;
            int rem = idx & 255;
            int r = rem >> 3, ch = rem & 7;
            const __nv_bfloat16* src = (arr ? Bl : Bh) + (size_t)(k0 + r) * N + bn + ch * 8;
            CP_ASYNC16(st + (uint32_t)((arr ? BL_O : BH_O) + r * BSTR + ch * 8) * 2, src);
        }
        CP_COMMIT();
    };

    prefetch(0);

    for (int it = 0; it < NIT; it++) {
        if (it + 1 < NIT) { prefetch(it + 1); CP_WAIT(1); }
        else              { CP_WAIT(0); }
        __syncthreads();

        const uint32_t st = base + (uint32_t)((it & 1) * STAGE_EL * 2);
        const uint32_t ah = st + AH_O * 2, al = st + AL_O * 2;
        const uint32_t bh = st + BH_O * 2, bl = st + BL_O * 2;

#pragma unroll
        for (int s = 0; s < 2; s++) {
            uint32_t afh[2][4], afl[2][4];
#pragma unroll
            for (int i = 0; i < 2; i++) {
                uint32_t off = (uint32_t)((a_row + i * 16) * ASTR + s * 16 + a_colp) * 2;
                LDSM_X4(afh[i][0], afh[i][1], afh[i][2], afh[i][3], ah + off);
                LDSM_X4(afl[i][0], afl[i][1], afl[i][2], afl[i][3], al + off);
            }
            uint32_t bfh[4][2], bfl[4][2];
#pragma unroll
            for (int n = 0; n < 4; n++) {
                uint32_t off = (uint32_t)((s * 16 + b_row) * BSTR + wn * 32 + n * 8) * 2;
                LDSM_X2T(bfh[n][0], bfh[n][1], bh + off);
                LDSM_X2T(bfl[n][0], bfl[n][1], bl + off);
            }
#pragma unroll
            for (int i = 0; i < 2; i++)
#pragma unroll
                for (int n = 0; n < 4; n++) {
                    MMA_BF16(acc[i][n][0], acc[i][n][1], acc[i][n][2], acc[i][n][3],
                             afh[i][0], afh[i][1], afh[i][2], afh[i][3],
                             bfh[n][0], bfh[n][1]);
                    MMA_BF16(acc[i][n][0], acc[i][n][1], acc[i][n][2], acc[i][n][3],
                             afh[i][0], afh[i][1], afh[i][2], afh[i][3],
                             bfl[n][0], bfl[n][1]);
                    MMA_BF16(acc[i][n][0], acc[i][n][1], acc[i][n][2], acc[i][n][3],
                             afl[i][0], afl[i][1], afl[i][2], afl[i][3],
                             bfh[n][0], bfh[n][1]);
                }
        }
        __syncthreads();
    }

    // ---- epilogue ----
#pragma unroll
    for (int i = 0; i < 2; i++) {
        int row0 = bm + wm * 32 + i * 16 + g;
#pragma unroll
        for (int n = 0; n < 4; n++) {
            int col = bn + wn * 32 + n * 8 + 2 * tg;
            if (MODE == 0) {
                float b0 = bias[col], b1 = bias[col + 1];
                float sc = (col < D) ? CSCALE : 1.0f;
                __nv_bfloat16* Cb = (__nv_bfloat16*)C0;
                uint32_t u;
                PACK_BF16X2(u, (acc[i][n][0] + b0) * sc, (acc[i][n][1] + b1) * sc);
                *(uint32_t*)(Cb + (size_t)row0 * N + col) = u;
                PACK_BF16X2(u, (acc[i][n][2] + b0) * sc, (acc[i][n][3] + b1) * sc);
                *(uint32_t*)(Cb + (size_t)(row0 + 8) * N + col) = u;
            } else if (MODE == 1) {
                float b0 = bias[col], b1 = bias[col + 1];
                float2 r0 = *(const float2*)(resid + (size_t)row0 * N + col);
                float2 r1 = *(const float2*)(resid + (size_t)(row0 + 8) * N + col);
                __nv_bfloat16* Yh = (__nv_bfloat16*)C0;
                __nv_bfloat16* Yl = (__nv_bfloat16*)C1;
                uint32_t uh, ul;
                split2(acc[i][n][0] + b0 + r0.x, acc[i][n][1] + b1 + r0.y, uh, ul);
                *(uint32_t*)(Yh + (size_t)row0 * N + col) = uh;
                *(uint32_t*)(Yl + (size_t)row0 * N + col) = ul;
                split2(acc[i][n][2] + b0 + r1.x, acc[i][n][3] + b1 + r1.y, uh, ul);
                *(uint32_t*)(Yh + (size_t)(row0 + 8) * N + col) = uh;
                *(uint32_t*)(Yl + (size_t)(row0 + 8) * N + col) = ul;
            } else {
                float* Cf = (float*)C0;
                float v0 = acc[i][n][0], v1 = acc[i][n][1];
                float v2 = acc[i][n][2], v3 = acc[i][n][3];
                v0 = v0 / (1.f + __expf(-v0));
                v1 = v1 / (1.f + __expf(-v1));
                v2 = v2 / (1.f + __expf(-v2));
                v3 = v3 / (1.f + __expf(-v3));
                Cf[(size_t)col * M + row0] = v0;
                Cf[(size_t)(col + 1) * M + row0] = v1;
                Cf[(size_t)col * M + row0 + 8] = v2;
                Cf[(size_t)(col + 1) * M + row0 + 8] = v3;
            }
        }
    }
}

// ---------------------------------------------------------------------------
// 3) bf16 mma.sync flash attention, cp.async double-buffered.
//    fp32 output epilogue (register-light; split done by split_attn_kernel).
// ---------------------------------------------------------------------------
#define KT 64
#define SSTR 88
#define VOFF (64 * SSTR)

__global__ __launch_bounds__(256, 2)
void flash_attn_mma(const __nv_bfloat16* __restrict__ qkvh, float* __restrict__ out) {
    __shared__ __nv_bfloat16 R0[128 * SSTR];
    __shared__ __nv_bfloat16 R1[128 * SSTR];

    const int tid = threadIdx.x;
    const int w = tid >> 5, lane = tid & 31;
    const int g = lane >> 2, tg = lane & 3;
    const int head = blockIdx.y;
    const int q0 = blockIdx.x * 128;

    const uint32_t r0s = smem_u32(R0), r1s = smem_u32(R1);

    for (int i = tid; i < 128 * 4; i += 256) {
        int r = i >> 2, c = (i & 3) << 1;
        *(uint32_t*)&R0[r * SSTR + 72 + c] = 0;
        if (r < KT) *(uint32_t*)&R1[r * SSTR + 72 + c] = 0;
    }

    {
        const char* gq = (const char*)(qkvh + (size_t)q0 * DQKV + head * DH);
        for (int idx = tid; idx < 128 * 9; idx += 256) {
            int r = idx / 9, ch = idx % 9;
            CP_ASYNC16(r0s + (uint32_t)(r * SSTR * 2 + ch * 16),
                       gq + (size_t)r * (DQKV * 2) + ch * 16);
        }
        CP_COMMIT();
    }
    {
        const char* gk = (const char*)(qkvh + D + head * DH);
        for (int idx = tid; idx < 2 * KT * 9; idx += 256) {
            int part = idx >= KT * 9;
            int rem = idx - part * KT * 9;
            int r = rem / 9, ch = rem % 9;
            CP_ASYNC16(r1s + (uint32_t)(part * VOFF * 2 + r * SSTR * 2 + ch * 16),
                       gk + (size_t)r * (DQKV * 2) + (size_t)part * (D * 2) + ch * 16);
        }
        CP_COMMIT();
    }
    CP_WAIT(0);
    __syncthreads();

    uint32_t qa[5][4];
    {
        int row = w * 16 + (lane & 7) + 8 * ((lane >> 3) & 1);
        int colp = 8 * (lane >> 4);
#pragma unroll
        for (int s = 0; s < 5; s++) {
            uint32_t a = r0s + (uint32_t)(row * SSTR + 16 * s + colp) * 2;
            LDSM_X4(qa[s][0], qa[s][1], qa[s][2], qa[s][3], a);
        }
    }
    __syncthreads();

    float oacc[9][4];
#pragma unroll
    for (int n = 0; n < 9; n++)
#pragma unroll
        for (int i = 0; i < 4; i++) oacc[n][i] = 0.f;
    float l0 = 0.f, l1 = 0.f;

    const int bl_row = lane & 7;
    const int bl_colp = 8 * ((lane >> 3) & 1);
    const int vt_row = lane & 15;

    for (int kb = 0; kb < L / KT; kb++) {
        if (kb + 1 < L / KT) {
            uint32_t dst = ((kb + 1) & 1) ? r0s : r1s;
            const char* gk = (const char*)(qkvh + (size_t)((kb + 1) * KT) * DQKV + D + head * DH);
            for (int idx = tid; idx < 2 * KT * 9; idx += 256) {
                int part = idx >= KT * 9;
                int rem = idx - part * KT * 9;
                int r = rem / 9, ch = rem % 9;
                CP_ASYNC16(dst + (uint32_t)(part * VOFF * 2 + r * SSTR * 2 + ch * 16),
                           gk + (size_t)r * (DQKV * 2) + (size_t)part * (D * 2) + ch * 16);
            }
            CP_COMMIT();
            CP_WAIT(1);
        } else {
            CP_WAIT(0);
        }
        __syncthreads();

        const uint32_t kbuf = (kb & 1) ? r0s : r1s;
        const uint32_t vbuf = kbuf + VOFF * 2;

        float sacc[8][4];
#pragma unroll
        for (int j = 0; j < 8; j++) {
#pragma unroll
            for (int i = 0; i < 4; i++) sacc[j][i] = 0.f;
#pragma unroll
            for (int s = 0; s < 5; s++) {
                uint32_t b0, b1;
                uint32_t a = kbuf + (uint32_t)((j * 8 + bl_row) * SSTR + 16 * s + bl_colp) * 2;
                LDSM_X2(b0, b1, a);
                MMA_BF16(sacc[j][0], sacc[j][1], sacc[j][2], sacc[j][3],
                         qa[s][0], qa[s][1], qa[s][2], qa[s][3], b0, b1);
            }
        }

        uint32_t pa[8], pb[8];
#pragma unroll
        for (int j = 0; j < 8; j++) {
            float p0 = fast_exp2(sacc[j][0]);
            float p1 = fast_exp2(sacc[j][1]);
            float p2 = fast_exp2(sacc[j][2]);
            float p3 = fast_exp2(sacc[j][3]);
            l0 += p0 + p1;
            l1 += p2 + p3;
            PACK_BF16X2(pa[j], p0, p1);
            PACK_BF16X2(pb[j], p2, p3);
        }

#pragma unroll
        for (int t = 0; t < 4; t++) {
            uint32_t a0 = pa[2 * t], a1 = pb[2 * t];
            uint32_t a2 = pa[2 * t + 1], a3 = pb[2 * t + 1];
#pragma unroll
            for (int n = 0; n < 9; n++) {
                uint32_t b0, b1;
                uint32_t a = vbuf + (uint32_t)((16 * t + vt_row) * SSTR + 8 * n) * 2;
                LDSM_X2T(b0, b1, a);
                MMA_BF16(oacc[n][0], oacc[n][1], oacc[n][2], oacc[n][3],
                         a0, a1, a2, a3, b0, b1);
            }
        }
        __syncthreads();
    }

    l0 += __shfl_xor_sync(0xffffffffu, l0, 1);
    l0 += __shfl_xor_sync(0xffffffffu, l0, 2);
    l1 += __shfl_xor_sync(0xffffffffu, l1, 1);
    l1 += __shfl_xor_sync(0xffffffffu, l1, 2);
    float inv0 = 1.f / l0, inv1 = 1.f / l1;

    int row0 = q0 + w * 16 + g;
    float* base0 = out + (size_t)row0 * D + head * DH + 2 * tg;
    float* base1 = base0 + 8 * (size_t)D;
#pragma unroll
    for (int n = 0; n < 9; n++) {
        *(float2*)(base0 + 8 * n) = make_float2(oacc[n][0] * inv0, oacc[n][1] * inv0);
        *(float2*)(base1 + 8 * n) = make_float2(oacc[n][2] * inv1, oacc[n][3] * inv1);
    }
}

// ---------------------------------------------------------------------------
extern "C" void kernel_launch(void* const* d_in, const int* in_sizes, int n_in,
                              void* d_out, int out_size) {
    const float* fea    = (const float*)d_in[0];
    const float* w_qkv  = (const float*)d_in[1];
    const float* b_qkv  = (const float*)d_in[2];
    const float* w_out  = (const float*)d_in[3];
    const float* b_out  = (const float*)d_in[4];
    const float* conv_w = (const float*)d_in[5];
    float* out = (float*)d_out;

    float *px, *pattn;
    __nv_bfloat16 *pxh, *pxl, *pqkvh, *pah, *pal, *pyh, *pyl;
    __nv_bfloat16 *pwqh, *pwql, *pwoh, *pwol, *pcwh, *pcwl;
    cudaGetSymbolAddress((void**)&px,    g_x);
    cudaGetSymbolAddress((void**)&pxh,   g_xh);
    cudaGetSymbolAddress((void**)&pxl,   g_xl);
    cudaGetSymbolAddress((void**)&pqkvh, g_qkvh);
    cudaGetSymbolAddress((void**)&pattn, g_attn);
    cudaGetSymbolAddress((void**)&pah,   g_attnh);
    cudaGetSymbolAddress((void**)&pal,   g_attnl);
    cudaGetSymbolAddress((void**)&pyh,   g_yh);
    cudaGetSymbolAddress((void**)&pyl,   g_yl);
    cudaGetSymbolAddress((void**)&pwqh,  g_wqh);
    cudaGetSymbolAddress((void**)&pwql,  g_wql);
    cudaGetSymbolAddress((void**)&pwoh,  g_woh);
    cudaGetSymbolAddress((void**)&pwol,  g_wol);
    cudaGetSymbolAddress((void**)&pcwh,  g_cwh);
    cudaGetSymbolAddress((void**)&pcwl,  g_cwl);

    cudaFuncSetAttribute(gemm_mma<0>, cudaFuncAttributeMaxDynamicSharedMemorySize, GEMM_SMEM);
    cudaFuncSetAttribute(gemm_mma<1>, cudaFuncAttributeMaxDynamicSharedMemorySize, GEMM_SMEM);
    cudaFuncSetAttribute(gemm_mma<2>, cudaFuncAttributeMaxDynamicSharedMemorySize, GEMM_SMEM);

    // 1) unfold -> x (fp32 + split bf16); pre-split weights
    build_x_kernel<<<(L * D + 255) / 256, 256>>>(fea);
    split_w_kernel<<<(NW1 + NW2 + NW3 + 255) / 256, 256>>>(w_qkv, w_out, conv_w);

    // 2) qkv = x @ w_qkv + b_qkv -> bf16, Q pre-scaled
    gemm_mma<0><<<dim3(DQKV / 64, L / 128), 256, GEMM_SMEM>>>(
        pxh, pxl, pwqh, pwql, b_qkv, nullptr, (void*)pqkvh, nullptr, L, DQKV, D);

    // 3) attention -> fp32 attn, then split to bf16 h/l
    flash_attn_mma<<<dim3(L / 128, NH), 256>>>(pqkvh, pattn);
    split_attn_kernel<<<(L * D / 4 + 255) / 256, 256>>>(pattn, pah, pal);

    // 4) y = attn @ w_out + b_out + x -> split bf16 y
    gemm_mma<1><<<dim3(D / 64, L / 128), 256, GEMM_SMEM>>>(
        pah, pal, pwoh, pwol, b_out, px, (void*)pyh, (void*)pyl, L, D, D);

    // 5) out = silu(y @ conv_w^T) stored as [128, 4096]
    gemm_mma<2><<<dim3(OUTC / 64, L / 128), 256, GEMM_SMEM>>>(
        pyh, pyl, pcwh, pcwl, nullptr, nullptr, (void*)out, nullptr, L, OUTC, D);
}

// round 15
// speedup vs baseline: 1.6867x; 1.1089x over previous
#include <cuda_runtime.h>
#include <cuda_bf16.h>
#include <cstdint>

#define L 4096
#define D 576
#define DQKV 1728
#define NH 8
#define DH 72
#define OUTC 128

// Scratch (no dynamic allocation allowed)
__device__ float g_x[L * D];                       // fp32 tokens (residual)
__device__ __nv_bfloat16 g_xh[L * D], g_xl[L * D]; // split tokens
__device__ __nv_bfloat16 g_qkvh[L * DQKV];         // bf16 qkv, Q pre-scaled
__device__ float g_attn[L * D];                    // fp32 attention output
__device__ __nv_bfloat16 g_attnh[L * D], g_attnl[L * D];
__device__ __nv_bfloat16 g_yh[L * D], g_yl[L * D];
__device__ __nv_bfloat16 g_wqh[D * DQKV], g_wql[D * DQKV];
__device__ __nv_bfloat16 g_woh[D * D], g_wol[D * D];
__device__ __nv_bfloat16 g_cwh[D * OUTC], g_cwl[D * OUTC];  // conv_w transposed [K][N]

#define CSCALE (0.11785113019775793f * 1.4426950408889634f)  // 72^-0.5 * log2e

// ---------------------------------------------------------------------------
// helpers
// ---------------------------------------------------------------------------
__device__ __forceinline__ uint32_t smem_u32(const void* p) {
    uint32_t a;
    asm("{ .reg .u64 t; cvta.to.shared.u64 t, %1; cvt.u32.u64 %0, t; }" : "=r"(a) : "l"(p));
    return a;
}

// 8-instruction exp2: magic-round + deg-3 poly + exponent splice.
// (0x4B400000 << 23) mod 2^32 == 0, so t_bits<<23 IS n<<23 -- no bias sub.
// max rel err ~2.5e-4, below P's bf16 rounding (2e-3).
__device__ __forceinline__ float exp2_fast(float s) {
    float t = __fadd_rn(s, 12582912.0f);
    float f = s - __fadd_rn(t, -12582912.0f);
    float r = fmaf(f, 0.0555041f, 0.2414265f);
    r = fmaf(f, r, 0.6931472f);
    r = fmaf(f, r, 1.0f);
    return __int_as_float(__float_as_int(r) + (__float_as_int(t) << 23));
}

// full-precision fast exp2 (kept for any wide-range use; not in flash loop)
__device__ __forceinline__ float fast_exp2(float x) {
    float t = __fadd_rn(x, 12582912.0f);
    int ni = __float_as_int(t) - 0x4B400000;
    float f = x - __fadd_rn(t, -12582912.0f);
    float y = f * 0.6931471805599453f;
    float p = 8.3333333e-3f;
    p = fmaf(p, y, 4.1666667e-2f);
    p = fmaf(p, y, 0.16666667f);
    p = fmaf(p, y, 0.5f);
    p = fmaf(p, y, 1.0f);
    p = fmaf(p, y, 1.0f);
    return __int_as_float(__float_as_int(p) + (ni << 23));
}

#define LDSM_X4(r0, r1, r2, r3, a) \
    asm volatile("ldmatrix.sync.aligned.m8n8.x4.shared.b16 {%0,%1,%2,%3}, [%4];" \
                 : "=r"(r0), "=r"(r1), "=r"(r2), "=r"(r3) : "r"(a))
#define LDSM_X2(r0, r1, a) \
    asm volatile("ldmatrix.sync.aligned.m8n8.x2.shared.b16 {%0,%1}, [%2];" \
                 : "=r"(r0), "=r"(r1) : "r"(a))
#define LDSM_X2T(r0, r1, a) \
    asm volatile("ldmatrix.sync.aligned.m8n8.x2.trans.shared.b16 {%0,%1}, [%2];" \
                 : "=r"(r0), "=r"(r1) : "r"(a))
#define LDSM_X4T(r0, r1, r2, r3, a) \
    asm volatile("ldmatrix.sync.aligned.m8n8.x4.trans.shared.b16 {%0,%1,%2,%3}, [%4];" \
                 : "=r"(r0), "=r"(r1), "=r"(r2), "=r"(r3) : "r"(a))
#define MMA_BF16(c0, c1, c2, c3, a0, a1, a2, a3, b0, b1) \
    asm volatile("mma.sync.aligned.m16n8k16.row.col.f32.bf16.bf16.f32 " \
                 "{%0,%1,%2,%3}, {%4,%5,%6,%7}, {%8,%9}, {%0,%1,%2,%3};" \
                 : "+f"(c0), "+f"(c1), "+f"(c2), "+f"(c3) \
                 : "r"(a0), "r"(a1), "r"(a2), "r"(a3), "r"(b0), "r"(b1))
#define PACK_BF16X2(d, lo, hi) \
    asm("cvt.rn.bf16x2.f32 %0, %1, %2;" : "=r"(d) : "f"(hi), "f"(lo))
#define CP_ASYNC16(sm, gm) \
    asm volatile("cp.async.cg.shared.global [%0], [%1], 16;" :: "r"(sm), "l"(gm) : "memory")
#define CP_COMMIT() asm volatile("cp.async.commit_group;" ::: "memory")
#define CP_WAIT(n)  asm volatile("cp.async.wait_group %0;" :: "n"(n) : "memory")

// split (x,y) -> packed bf16x2 hi + lo-of-residual
__device__ __forceinline__ void split2(float x, float y, uint32_t& hi, uint32_t& lo) {
    __nv_bfloat16 xh = __float2bfloat16(x), yh = __float2bfloat16(y);
    float xr = x - __bfloat162float(xh), yr = y - __bfloat162float(yh);
    PACK_BF16X2(hi, __bfloat162float(xh), __bfloat162float(yh));
    PACK_BF16X2(lo, xr, yr);
}

// ---------------------------------------------------------------------------
// 1) unfold(3x3, pad=1, stride=2) -> x[L,576] fp32 + split bf16
// ---------------------------------------------------------------------------
__global__ void build_x_kernel(const float* __restrict__ fea) {
    int idx = blockIdx.x * blockDim.x + threadIdx.x;
    if (idx >= L * D) return;
    int l = idx / D, d = idx % D;
    int c = d / 9, k = d % 9;
    int ki = k / 3, kj = k % 3;
    int ho = l >> 6, wo = l & 63;
    int h = 2 * ho + ki - 1, w = 2 * wo + kj - 1;
    float v = 0.f;
    if ((unsigned)h < 128u && (unsigned)w < 128u)
        v = fea[(c << 14) + (h << 7) + w];
    g_x[idx] = v;
    __nv_bfloat16 hb = __float2bfloat16(v);
    g_xh[idx] = hb;
    g_xl[idx] = __float2bfloat16(v - __bfloat162float(hb));
}

// ---------------------------------------------------------------------------
// 1b) pre-split weights
// ---------------------------------------------------------------------------
#define NW1 (D * DQKV)
#define NW2 (D * D)
#define NW3 (OUTC * D)
__global__ void split_w_kernel(const float* __restrict__ w_qkv,
                               const float* __restrict__ w_out,
                               const float* __restrict__ conv_w) {
    int i = blockIdx.x * blockDim.x + threadIdx.x;
    if (i < NW1) {
        float v = w_qkv[i];
        __nv_bfloat16 hb = __float2bfloat16(v);
        g_wqh[i] = hb;
        g_wql[i] = __float2bfloat16(v - __bfloat162float(hb));
    } else if (i < NW1 + NW2) {
        int e = i - NW1;
        float v = w_out[e];
        __nv_bfloat16 hb = __float2bfloat16(v);
        g_woh[e] = hb;
        g_wol[e] = __float2bfloat16(v - __bfloat162float(hb));
    } else if (i < NW1 + NW2 + NW3) {
        int e = i - NW1 - NW2;
        int n = e / D, k = e % D;
        float v = conv_w[e];
        __nv_bfloat16 hb = __float2bfloat16(v);
        int o = k * OUTC + n;
        g_cwh[o] = hb;
        g_cwl[o] = __float2bfloat16(v - __bfloat162float(hb));
    }
}

// ---------------------------------------------------------------------------
// 1c) split attn fp32 -> bf16 h/l
// ---------------------------------------------------------------------------
__global__ void split_attn_kernel(const float* __restrict__ a,
                                  __nv_bfloat16* __restrict__ h,
                                  __nv_bfloat16* __restrict__ l) {
    int i = (blockIdx.x * blockDim.x + threadIdx.x) * 4;
    if (i >= L * D) return;
    float4 v = *(const float4*)(a + i);
    uint32_t uh0, ul0, uh1, ul1;
    split2(v.x, v.y, uh0, ul0);
    split2(v.z, v.w, uh1, ul1);
    *(uint32_t*)(h + i)     = uh0;
    *(uint32_t*)(h + i + 2) = uh1;
    *(uint32_t*)(l + i)     = ul0;
    *(uint32_t*)(l + i + 2) = ul1;
}

// ---------------------------------------------------------------------------
// 2) Split-bf16 tensor-core GEMM, cp.async 2-stage pipeline. (unchanged)
// ---------------------------------------------------------------------------
#define ASTR 40
#define BSTR 72
#define AH_O 0
#define AL_O (128 * ASTR)
#define BH_O (2 * 128 * ASTR)
#define BL_O (2 * 128 * ASTR + 32 * BSTR)
#define STAGE_EL (2 * 128 * ASTR + 2 * 32 * BSTR)
#define GEMM_SMEM (STAGE_EL * 2 * 2)

template <int MODE>
__global__ __launch_bounds__(256, 2)
void gemm_mma(const __nv_bfloat16* __restrict__ Ah, const __nv_bfloat16* __restrict__ Al,
              const __nv_bfloat16* __restrict__ Bh, const __nv_bfloat16* __restrict__ Bl,
              const float* __restrict__ bias, const float* __restrict__ resid,
              void* __restrict__ C0, void* __restrict__ C1, int M, int N, int K) {
    extern __shared__ __nv_bfloat16 sm[];
    const uint32_t base = smem_u32(sm);

    const int tid = threadIdx.x;
    const int w = tid >> 5, lane = tid & 31;
    const int wm = w & 3, wn = w >> 2;
    const int g = lane >> 2, tg = lane & 3;
    const int bm = blockIdx.y * 128, bn = blockIdx.x * 64;

    float acc[2][4][4];
#pragma unroll
    for (int i = 0; i < 2; i++)
#pragma unroll
        for (int n = 0; n < 4; n++)
#pragma unroll
            for (int c = 0; c < 4; c++) acc[i][n][c] = 0.f;

    const int a_row = wm * 32 + (lane & 15);
    const int a_colp = 8 * (lane >> 4);
    const int b_row = lane & 15;
    const int NIT = K / 32;

    auto prefetch = [&](int it) {
        const int k0 = it * 32;
        const uint32_t st = base + (uint32_t)((it & 1) * STAGE_EL * 2);
#pragma unroll
        for (int t = 0; t < 4; t++) {
            int idx = tid + t * 256;
            int arr = idx >> 9;
            int rem = idx & 511;
            int r = rem >> 2, ch = rem & 3;
            const __nv_bfloat16* src = (arr ? Al : Ah) + (size_t)(bm + r) * K + k0 + ch * 8;
            CP_ASYNC16(st + (uint32_t)((arr ? AL_O : AH_O) + r * ASTR + ch * 8) * 2, src);
        }
#pragma unroll
        for (int t = 0; t < 2; t++) {
            int idx = tid + t * 256;
            int arr = idx >> 8;
            int rem = idx & 255;
            int r = rem >> 3, ch = rem & 7;
            const __nv_bfloat16* src = (arr ? Bl : Bh) + (size_t)(k0 + r) * N + bn + ch * 8;
            CP_ASYNC16(st + (uint32_t)((arr ? BL_O : BH_O) + r * BSTR + ch * 8) * 2, src);
        }
        CP_COMMIT();
    };

    prefetch(0);

    for (int it = 0; it < NIT; it++) {
        if (it + 1 < NIT) { prefetch(it + 1); CP_WAIT(1); }
        else              { CP_WAIT(0); }
        __syncthreads();

        const uint32_t st = base + (uint32_t)((it & 1) * STAGE_EL * 2);
        const uint32_t ah = st + AH_O * 2, al = st + AL_O * 2;
        const uint32_t bh = st + BH_O * 2, bl = st + BL_O * 2;

#pragma unroll
        for (int s = 0; s < 2; s++) {
            uint32_t afh[2][4], afl[2][4];
#pragma unroll
            for (int i = 0; i < 2; i++) {
                uint32_t off = (uint32_t)((a_row + i * 16) * ASTR + s * 16 + a_colp) * 2;
                LDSM_X4(afh[i][0], afh[i][1], afh[i][2], afh[i][3], ah + off);
                LDSM_X4(afl[i][0], afl[i][1], afl[i][2], afl[i][3], al + off);
            }
            uint32_t bfh[4][2], bfl[4][2];
#pragma unroll
            for (int n = 0; n < 4; n++) {
                uint32_t off = (uint32_t)((s * 16 + b_row) * BSTR + wn * 32 + n * 8) * 2;
                LDSM_X2T(bfh[n][0], bfh[n][1], bh + off);
                LDSM_X2T(bfl[n][0], bfl[n][1], bl + off);
            }
#pragma unroll
            for (int i = 0; i < 2; i++)
#pragma unroll
                for (int n = 0; n < 4; n++) {
                    MMA_BF16(acc[i][n][0], acc[i][n][1], acc[i][n][2], acc[i][n][3],
                             afh[i][0], afh[i][1], afh[i][2], afh[i][3],
                             bfh[n][0], bfh[n][1]);
                    MMA_BF16(acc[i][n][0], acc[i][n][1], acc[i][n][2], acc[i][n][3],
                             afh[i][0], afh[i][1], afh[i][2], afh[i][3],
                             bfl[n][0], bfl[n][1]);
                    MMA_BF16(acc[i][n][0], acc[i][n][1], acc[i][n][2], acc[i][n][3],
                             afl[i][0], afl[i][1], afl[i][2], afl[i][3],
                             bfh[n][0], bfh[n][1]);
                }
        }
        __syncthreads();
    }

#pragma unroll
    for (int i = 0; i < 2; i++) {
        int row0 = bm + wm * 32 + i * 16 + g;
#pragma unroll
        for (int n = 0; n < 4; n++) {
            int col = bn + wn * 32 + n * 8 + 2 * tg;
            if (MODE == 0) {
                float b0 = bias[col], b1 = bias[col + 1];
                float sc = (col < D) ? CSCALE : 1.0f;
                __nv_bfloat16* Cb = (__nv_bfloat16*)C0;
                uint32_t u;
                PACK_BF16X2(u, (acc[i][n][0] + b0) * sc, (acc[i][n][1] + b1) * sc);
                *(uint32_t*)(Cb + (size_t)row0 * N + col) = u;
                PACK_BF16X2(u, (acc[i][n][2] + b0) * sc, (acc[i][n][3] + b1) * sc);
                *(uint32_t*)(Cb + (size_t)(row0 + 8) * N + col) = u;
            } else if (MODE == 1) {
                float b0 = bias[col], b1 = bias[col + 1];
                float2 r0 = *(const float2*)(resid + (size_t)row0 * N + col);
                float2 r1 = *(const float2*)(resid + (size_t)(row0 + 8) * N + col);
                __nv_bfloat16* Yh = (__nv_bfloat16*)C0;
                __nv_bfloat16* Yl = (__nv_bfloat16*)C1;
                uint32_t uh, ul;
                split2(acc[i][n][0] + b0 + r0.x, acc[i][n][1] + b1 + r0.y, uh, ul);
                *(uint32_t*)(Yh + (size_t)row0 * N + col) = uh;
                *(uint32_t*)(Yl + (size_t)row0 * N + col) = ul;
                split2(acc[i][n][2] + b0 + r1.x, acc[i][n][3] + b1 + r1.y, uh, ul);
                *(uint32_t*)(Yh + (size_t)(row0 + 8) * N + col) = uh;
                *(uint32_t*)(Yl + (size_t)(row0 + 8) * N + col) = ul;
            } else {
                float* Cf = (float*)C0;
                float v0 = acc[i][n][0], v1 = acc[i][n][1];
                float v2 = acc[i][n][2], v3 = acc[i][n][3];
                v0 = v0 / (1.f + __expf(-v0));
                v1 = v1 / (1.f + __expf(-v1));
                v2 = v2 / (1.f + __expf(-v2));
                v3 = v3 / (1.f + __expf(-v3));
                Cf[(size_t)col * M + row0] = v0;
                Cf[(size_t)(col + 1) * M + row0] = v1;
                Cf[(size_t)col * M + row0 + 8] = v2;
                Cf[(size_t)(col + 1) * M + row0 + 8] = v3;
            }
        }
    }
}

// ---------------------------------------------------------------------------
// 3) bf16 mma.sync flash attention, cp.async double-buffered.
//    Lean issue stream: x4 ldmatrix, 8-instr exp2 fused per j-pair,
//    li via ones-column in V (10th PV n-tile, fp32 MMA accumulator).
// ---------------------------------------------------------------------------
#define KT 64
#define SSTR 88
#define VOFF (64 * SSTR)

__global__ __launch_bounds__(256, 2)
void flash_attn_mma(const __nv_bfloat16* __restrict__ qkvh, float* __restrict__ out) {
    __shared__ __nv_bfloat16 R0[128 * SSTR];
    __shared__ __nv_bfloat16 R1[128 * SSTR];

    const int tid = threadIdx.x;
    const int w = tid >> 5, lane = tid & 31;
    const int g = lane >> 2, tg = lane & 3;
    const int head = blockIdx.y;
    const int q0 = blockIdx.x * 128;

    const uint32_t r0s = smem_u32(R0), r1s = smem_u32(R1);

    // zero pad cols 72..79 of ALL rows in both buffers (Q pad, K pad, V pad)
    for (int i = tid; i < 128 * 4 * 2; i += 256) {
        int buf = i >= 128 * 4;
        int rem = i - buf * 128 * 4;
        int r = rem >> 2, c = (rem & 3) << 1;
        if (!buf) *(uint32_t*)&R0[r * SSTR + 72 + c] = 0;
        else      *(uint32_t*)&R1[r * SSTR + 72 + c] = 0;
    }

    // Q fill via cp.async
    {
        const char* gq = (const char*)(qkvh + (size_t)q0 * DQKV + head * DH);
        for (int idx = tid; idx < 128 * 9; idx += 256) {
            int r = idx / 9, ch = idx % 9;
            CP_ASYNC16(r0s + (uint32_t)(r * SSTR * 2 + ch * 16),
                       gq + (size_t)r * (DQKV * 2) + ch * 16);
        }
        CP_COMMIT();
    }
    // KV fill for kb=0 into R1
    {
        const char* gk = (const char*)(qkvh + D + head * DH);
        for (int idx = tid; idx < 2 * KT * 9; idx += 256) {
            int part = idx >= KT * 9;
            int rem = idx - part * KT * 9;
            int r = rem / 9, ch = rem % 9;
            CP_ASYNC16(r1s + (uint32_t)(part * VOFF * 2 + r * SSTR * 2 + ch * 16),
                       gk + (size_t)r * (DQKV * 2) + (size_t)part * (D * 2) + ch * 16);
        }
        CP_COMMIT();
    }
    CP_WAIT(0);
    __syncthreads();

    uint32_t qa[5][4];
    {
        int row = w * 16 + (lane & 7) + 8 * ((lane >> 3) & 1);
        int colp = 8 * (lane >> 4);
#pragma unroll
        for (int s = 0; s < 5; s++) {
            uint32_t a = r0s + (uint32_t)(row * SSTR + 16 * s + colp) * 2;
            LDSM_X4(qa[s][0], qa[s][1], qa[s][2], qa[s][3], a);
        }
    }
    __syncthreads();   // Q reads done; safe to overwrite R0 cols 0..71 + set ones

    // ones-column (col 72) in V region of both buffers; li comes from PV MMA.
    // cp.async refills touch only cols 0..71, so this survives all tiles.
    for (int r = tid; r < 64; r += 256) {
        R0[VOFF + r * SSTR + 72] = __float2bfloat16(1.0f);
        R1[VOFF + r * SSTR + 72] = __float2bfloat16(1.0f);
    }
    __syncthreads();

    float oacc[10][4];
#pragma unroll
    for (int n = 0; n < 10; n++)
#pragma unroll
        for (int i = 0; i < 4; i++) oacc[n][i] = 0.f;

    // hoisted per-warp ldmatrix base offsets (element units)
    const uint32_t kbase_off = (uint32_t)(((lane >> 4) * 8 + (lane & 7)) * SSTR
                                          + 8 * ((lane >> 3) & 1)) * 2;
    const uint32_t vbase_off = (uint32_t)((lane & 15) * SSTR + 8 * (lane >> 4)) * 2;

    for (int kb = 0; kb < L / KT; kb++) {
        if (kb + 1 < L / KT) {
            uint32_t dst = ((kb + 1) & 1) ? r0s : r1s;
            const char* gk = (const char*)(qkvh + (size_t)((kb + 1) * KT) * DQKV + D + head * DH);
            for (int idx = tid; idx < 2 * KT * 9; idx += 256) {
                int part = idx >= KT * 9;
                int rem = idx - part * KT * 9;
                int r = rem / 9, ch = rem % 9;
                CP_ASYNC16(dst + (uint32_t)(part * VOFF * 2 + r * SSTR * 2 + ch * 16),
                           gk + (size_t)r * (DQKV * 2) + (size_t)part * (D * 2) + ch * 16);
            }
            CP_COMMIT();
            CP_WAIT(1);
        } else {
            CP_WAIT(0);
        }
        __syncthreads();

        const uint32_t kbuf = (kb & 1) ? r0s : r1s;
        const uint32_t vbuf = kbuf + VOFF * 2;
        const uint32_t kaddr = kbuf + kbase_off;
        const uint32_t vaddr = vbuf + vbase_off;

        // ---- S = Q@K^T fused with exp+pack, j-pair at a time ----
        uint32_t pa[8], pb[8];
#pragma unroll
        for (int jp = 0; jp < 4; jp++) {
            float sA[4] = {0.f, 0.f, 0.f, 0.f};
            float sB[4] = {0.f, 0.f, 0.f, 0.f};
#pragma unroll
            for (int s = 0; s < 5; s++) {
                uint32_t b0, b1, b2, b3;
                LDSM_X4(b0, b1, b2, b3,
                        kaddr + (uint32_t)(jp * 16 * SSTR + 16 * s) * 2);
                MMA_BF16(sA[0], sA[1], sA[2], sA[3],
                         qa[s][0], qa[s][1], qa[s][2], qa[s][3], b0, b1);
                MMA_BF16(sB[0], sB[1], sB[2], sB[3],
                         qa[s][0], qa[s][1], qa[s][2], qa[s][3], b2, b3);
            }
            PACK_BF16X2(pa[2 * jp],     exp2_fast(sA[0]), exp2_fast(sA[1]));
            PACK_BF16X2(pb[2 * jp],     exp2_fast(sA[2]), exp2_fast(sA[3]));
            PACK_BF16X2(pa[2 * jp + 1], exp2_fast(sB[0]), exp2_fast(sB[1]));
            PACK_BF16X2(pb[2 * jp + 1], exp2_fast(sB[2]), exp2_fast(sB[3]));
        }

        // ---- O += P @ V (10 n-tiles; n=9 is the ones-column -> li) ----
#pragma unroll
        for (int t = 0; t < 4; t++) {
            uint32_t a0 = pa[2 * t], a1 = pb[2 * t];
            uint32_t a2 = pa[2 * t + 1], a3 = pb[2 * t + 1];
#pragma unroll
            for (int np = 0; np < 4; np++) {
                uint32_t b0, b1, b2, b3;
                LDSM_X4T(b0, b1, b2, b3,
                         vaddr + (uint32_t)(16 * t * SSTR + 16 * np) * 2);
                MMA_BF16(oacc[2 * np][0], oacc[2 * np][1], oacc[2 * np][2], oacc[2 * np][3],
                         a0, a1, a2, a3, b0, b1);
                MMA_BF16(oacc[2 * np + 1][0], oacc[2 * np + 1][1],
                         oacc[2 * np + 1][2], oacc[2 * np + 1][3],
                         a0, a1, a2, a3, b2, b3);
            }
            {
                uint32_t b0, b1;
                LDSM_X2T(b0, b1, vaddr + (uint32_t)(16 * t * SSTR + 64) * 2);
                MMA_BF16(oacc[8][0], oacc[8][1], oacc[8][2], oacc[8][3],
                         a0, a1, a2, a3, b0, b1);
                LDSM_X2T(b0, b1, vaddr + (uint32_t)(16 * t * SSTR + 72) * 2);
                MMA_BF16(oacc[9][0], oacc[9][1], oacc[9][2], oacc[9][3],
                         a0, a1, a2, a3, b0, b1);
            }
        }
        __syncthreads();
    }

    // li = ones-column sums (live in tg==0 lanes, col 72) -> broadcast
    float l0 = __shfl_sync(0xffffffffu, oacc[9][0], (lane >> 2) << 2);
    float l1 = __shfl_sync(0xffffffffu, oacc[9][2], (lane >> 2) << 2);
    float inv0 = 1.f / l0, inv1 = 1.f / l1;

    int row0 = q0 + w * 16 + g;
    float* base0 = out + (size_t)row0 * D + head * DH + 2 * tg;
    float* base1 = base0 + 8 * (size_t)D;
#pragma unroll
    for (int n = 0; n < 9; n++) {
        *(float2*)(base0 + 8 * n) = make_float2(oacc[n][0] * inv0, oacc[n][1] * inv0);
        *(float2*)(base1 + 8 * n) = make_float2(oacc[n][2] * inv1, oacc[n][3] * inv1);
    }
}

// ---------------------------------------------------------------------------
extern "C" void kernel_launch(void* const* d_in, const int* in_sizes, int n_in,
                              void* d_out, int out_size) {
    const float* fea    = (const float*)d_in[0];
    const float* w_qkv  = (const float*)d_in[1];
    const float* b_qkv  = (const float*)d_in[2];
    const float* w_out  = (const float*)d_in[3];
    const float* b_out  = (const float*)d_in[4];
    const float* conv_w = (const float*)d_in[5];
    float* out = (float*)d_out;

    float *px, *pattn;
    __nv_bfloat16 *pxh, *pxl, *pqkvh, *pah, *pal, *pyh, *pyl;
    __nv_bfloat16 *pwqh, *pwql, *pwoh, *pwol, *pcwh, *pcwl;
    cudaGetSymbolAddress((void**)&px,    g_x);
    cudaGetSymbolAddress((void**)&pxh,   g_xh);
    cudaGetSymbolAddress((void**)&pxl,   g_xl);
    cudaGetSymbolAddress((void**)&pqkvh, g_qkvh);
    cudaGetSymbolAddress((void**)&pattn, g_attn);
    cudaGetSymbolAddress((void**)&pah,   g_attnh);
    cudaGetSymbolAddress((void**)&pal,   g_attnl);
    cudaGetSymbolAddress((void**)&pyh,   g_yh);
    cudaGetSymbolAddress((void**)&pyl,   g_yl);
    cudaGetSymbolAddress((void**)&pwqh,  g_wqh);
    cudaGetSymbolAddress((void**)&pwql,  g_wql);
    cudaGetSymbolAddress((void**)&pwoh,  g_woh);
    cudaGetSymbolAddress((void**)&pwol,  g_wol);
    cudaGetSymbolAddress((void**)&pcwh,  g_cwh);
    cudaGetSymbolAddress((void**)&pcwl,  g_cwl);

    cudaFuncSetAttribute(gemm_mma<0>, cudaFuncAttributeMaxDynamicSharedMemorySize, GEMM_SMEM);
    cudaFuncSetAttribute(gemm_mma<1>, cudaFuncAttributeMaxDynamicSharedMemorySize, GEMM_SMEM);
    cudaFuncSetAttribute(gemm_mma<2>, cudaFuncAttributeMaxDynamicSharedMemorySize, GEMM_SMEM);

    // 1) unfold -> x (fp32 + split bf16); pre-split weights
    build_x_kernel<<<(L * D + 255) / 256, 256>>>(fea);
    split_w_kernel<<<(NW1 + NW2 + NW3 + 255) / 256, 256>>>(w_qkv, w_out, conv_w);

    // 2) qkv = x @ w_qkv + b_qkv -> bf16, Q pre-scaled
    gemm_mma<0><<<dim3(DQKV / 64, L / 128), 256, GEMM_SMEM>>>(
        pxh, pxl, pwqh, pwql, b_qkv, nullptr, (void*)pqkvh, nullptr, L, DQKV, D);

    // 3) attention -> fp32 attn, then split to bf16 h/l
    flash_attn_mma<<<dim3(L / 128, NH), 256>>>(pqkvh, pattn);
    split_attn_kernel<<<(L * D / 4 + 255) / 256, 256>>>(pattn, pah, pal);

    // 4) y = attn @ w_out + b_out + x -> split bf16 y
    gemm_mma<1><<<dim3(D / 64, L / 128), 256, GEMM_SMEM>>>(
        pah, pal, pwoh, pwol, b_out, px, (void*)pyh, (void*)pyl, L, D, D);

    // 5) out = silu(y @ conv_w^T) stored as [128, 4096]
    gemm_mma<2><<<dim3(OUTC / 64, L / 128), 256, GEMM_SMEM>>>(
        pyh, pyl, pcwh, pcwl, nullptr, nullptr, (void*)out, nullptr, L, OUTC, D);
}